// round 13
// baseline (speedup 1.0000x reference)
#include <cuda_runtime.h>
#include <math.h>

#define NB_MAX 400
#define WKER   0.05f
#define INV_WKER 20.0f
#define CUT    0.225f          // 4.5 sigma truncation
#define GNORM  7.9788456080f   // 1/(0.05*sqrt(2*pi))
#define PI_F   3.14159265358979f
#define HF     0.01f           // fine-bin width = sigma/5
#define INV_HF 100.0f
#define MFINE_MAX 1152
#define HGRID  444             // 3 blocks x 148 SMs, all resident

__device__ float    g_fine[MFINE_MAX]; // CIC pair cloud (zero at load; sf re-zeroes)
__device__ float    g_A[NB_MAX];       // integrand weights (written by conv)
__device__ unsigned g_ticket;          // row work-queue (zero at load; sf resets)

// ---------------------------------------------------------------------------
// Kernel 1: MIC pair distances + CIC deposit into per-block shared fine
// histogram. Rows distributed by a dynamic ticket (perfect SM balance).
// Each thread processes 4 consecutive atoms per chunk via 3x LDG.128
// (4 independent MIC chains -> ILP), rsqrt-based distance.
// ---------------------------------------------------------------------------
__global__ void __launch_bounds__(256)
hist_kernel(const float* __restrict__ pos, const float* __restrict__ cell,
            const float* __restrict__ rb, int N, int nb) {
    __shared__ float    s_fine[MFINE_MAX];
    __shared__ unsigned s_u;
    int t = threadIdx.x;

    for (int k = t; k < MFINE_MAX; k += 256) s_fine[k] = 0.0f;

    // uniform per-thread cell handling (ptxas promotes to uniform regs)
    float m[9];
    #pragma unroll
    for (int i = 0; i < 9; i++) m[i] = __ldg(cell + i);
    const bool diag = (m[1]==0.f && m[2]==0.f && m[3]==0.f &&
                       m[5]==0.f && m[6]==0.f && m[7]==0.f);
    float ci[9];
    {
        float c00 =  (m[4]*m[8] - m[5]*m[7]);
        float c01 = -(m[3]*m[8] - m[5]*m[6]);
        float c02 =  (m[3]*m[7] - m[4]*m[6]);
        float det = m[0]*c00 + m[1]*c01 + m[2]*c02;
        float id  = 1.0f / det;
        ci[0] =  c00 * id;
        ci[1] = -(m[1]*m[8] - m[2]*m[7]) * id;
        ci[2] =  (m[1]*m[5] - m[2]*m[4]) * id;
        ci[3] =  c01 * id;
        ci[4] =  (m[0]*m[8] - m[2]*m[6]) * id;
        ci[5] = -(m[0]*m[5] - m[2]*m[3]) * id;
        ci[6] =  c02 * id;
        ci[7] = -(m[0]*m[7] - m[1]*m[6]) * id;
        ci[8] =  (m[0]*m[4] - m[1]*m[3]) * id;
    }
    const float Lx = m[0], Ly = m[4], Lz = m[8];
    const float iLx = 1.0f / Lx, iLy = 1.0f / Ly, iLz = 1.0f / Lz;

    const float minb  = __ldg(rb)          - 3.0f * WKER;
    const float maxb  = __ldg(rb + nb - 1) + 3.0f * WKER;
    const float minb2 = (minb > 0.0f) ? minb * minb : -1.0f;
    const float maxb2 = maxb * maxb;
    int  M = (int)ceilf(maxb * INV_HF) + 1;
    if (M > MFINE_MAX) M = MFINE_MAX;
    const int Mm2 = M - 2;

    __syncthreads();

    const float4* __restrict__ p4 = (const float4*)pos;

    float xi = 0.f, yi = 0.f, zi = 0.f;

    // pair computation against current row atom (xi,yi,zi)
    auto dopair = [&](float xj, float yj, float zj) {
        float dx = xj - xi, dy = yj - yi, dz = zj - zi;
        float d2;
        if (diag) {
            dx -= Lx * rintf(dx * iLx);
            dy -= Ly * rintf(dy * iLy);
            dz -= Lz * rintf(dz * iLz);
            d2 = dx*dx + dy*dy + dz*dz;
        } else {
            float fx = dx*ci[0] + dy*ci[3] + dz*ci[6];
            float fy = dx*ci[1] + dy*ci[4] + dz*ci[7];
            float fz = dx*ci[2] + dy*ci[5] + dz*ci[8];
            fx -= rintf(fx); fy -= rintf(fy); fz -= rintf(fz);
            float mx = fx*m[0] + fy*m[3] + fz*m[6];
            float my = fx*m[1] + fy*m[4] + fz*m[7];
            float mz = fx*m[2] + fy*m[5] + fz*m[8];
            d2 = mx*mx + my*my + mz*mz;
        }
        if (d2 > minb2 && d2 < maxb2) {          // exact reference window
            float dd = d2 + 1e-10f;
            float d  = dd * rsqrtf(dd);
            float u  = fmaf(d, INV_HF, -0.5f);
            int  ml  = __float2int_rd(u);
            float f  = u - (float)ml;
            if (ml > Mm2) ml = Mm2;
            int  m0  = ml > 0 ? ml : 0;
            atomicAdd(&s_fine[m0],     1.0f - f);
            atomicAdd(&s_fine[ml + 1], f);
        }
    };

    while (true) {
        if (t == 0) s_u = atomicAdd(&g_ticket, 1u);
        __syncthreads();
        int i = (int)s_u;
        __syncthreads();
        if (i >= N - 1) break;

        xi = __ldg(pos + 3*i + 0);
        yi = __ldg(pos + 3*i + 1);
        zi = __ldg(pos + 3*i + 2);

        int j0 = i + 1;
        int c0 = (j0 + 3) & ~3;                  // first 4-aligned atom
        int Nc = N & ~3;

        // scalar preamble [j0, min(c0,N))
        {
            int j = j0 + t;
            if (j < c0 && j < N)
                dopair(__ldg(pos + 3*j), __ldg(pos + 3*j + 1), __ldg(pos + 3*j + 2));
        }
        // vectorized main: 4 atoms per thread-chunk via 3x LDG.128
        for (int c = c0 + 4*t; c < Nc; c += 1024) {
            int b = 3 * (c >> 2);
            float4 q0 = __ldg(p4 + b);
            float4 q1 = __ldg(p4 + b + 1);
            float4 q2 = __ldg(p4 + b + 2);
            dopair(q0.x, q0.y, q0.z);
            dopair(q0.w, q1.x, q1.y);
            dopair(q1.z, q1.w, q2.x);
            dopair(q2.y, q2.z, q2.w);
        }
        // scalar tail [max(Nc,c0), N)
        {
            int ts = Nc > c0 ? Nc : c0;
            int j  = ts + t;
            if (j < N)
                dopair(__ldg(pos + 3*j), __ldg(pos + 3*j + 1), __ldg(pos + 3*j + 2));
        }
    }
    __syncthreads();

    // coalesced, distinct-address merge into global
    for (int k = t; k < M; k += 256) {
        float v = s_fine[k];
        if (v != 0.0f) atomicAdd(&g_fine[k], v);
    }
}

// ---------------------------------------------------------------------------
// Kernel 2: gather convolution + G + integrand weights.
//   hist_k = GNORM * sum_m fine[m] * exp(-0.5*((r_k-c_m)/w)^2), |r_k-c_m|<=CUT
//   G_k    = coeff * (vol/n_pairs * hist_k / (4 pi r_k^2) - 1)   -> out[k]
//   A_k    = 4 pi rho * w_k * r_k * G_k                          -> g_A[k]
// ---------------------------------------------------------------------------
__global__ void __launch_bounds__(128)
conv_kernel(const float* __restrict__ cell, const float* __restrict__ rb,
            float* __restrict__ out, int nb, int N, float n_pairs) {
    __shared__ float s_red[4];
    int k = blockIdx.x;
    int t = threadIdx.x;
    float r = __ldg(rb + k);
    float maxb = __ldg(rb + nb - 1) + 3.0f * WKER;
    int M = (int)ceilf(maxb * INV_HF) + 1;
    if (M > MFINE_MAX) M = MFINE_MAX;

    int mlo = (int)ceilf ((r - CUT) * INV_HF - 0.5f);
    int mhi = (int)floorf((r + CUT) * INV_HF - 0.5f);
    mlo = mlo < 0 ? 0 : mlo;
    mhi = mhi > M - 1 ? M - 1 : mhi;

    float acc = 0.0f;
    for (int mm = mlo + t; mm <= mhi; mm += 128) {
        float c = ((float)mm + 0.5f) * HF;
        float u = (r - c) * INV_WKER;
        acc += g_fine[mm] * __expf(-0.5f * u * u);
    }
    #pragma unroll
    for (int o = 16; o > 0; o >>= 1)
        acc += __shfl_xor_sync(0xffffffff, acc, o);
    if ((t & 31) == 0) s_red[t >> 5] = acc;
    __syncthreads();
    if (t == 0) {
        float hist = GNORM * (s_red[0] + s_red[1] + s_red[2] + s_red[3]);
        float m0 = cell[0], m1 = cell[1], m2 = cell[2];
        float m3 = cell[3], m4 = cell[4], m5 = cell[5];
        float m6 = cell[6], m7 = cell[7], m8 = cell[8];
        float det = m0*(m4*m8 - m5*m7) - m1*(m3*m8 - m5*m6) + m2*(m3*m7 - m4*m6);
        float vol = fabsf(det);
        float pref  = vol / n_pairs / (4.0f * PI_F);
        float coeff = 5.803f * 5.803f * 0.01f;
        float rho4p = 4.0f * PI_F * ((float)N / vol);
        float G = coeff * (pref * hist / (r * r) - 1.0f);
        out[k] = G;
        float xm = (k > 0)      ? __ldg(rb + k - 1) : r;
        float xp = (k < nb - 1) ? __ldg(rb + k + 1) : r;
        g_A[k] = rho4p * 0.5f * (xp - xm) * r * G;
    }
}

// ---------------------------------------------------------------------------
// Kernel 3: S(Q) = 1 + (1/(Q+1e-10)) * sum_k A_k sin(Q r_k); F = Q (S-1).
// Also re-zeroes g_fine and g_ticket for the next graph replay.
// ---------------------------------------------------------------------------
__global__ void __launch_bounds__(128)
sf_kernel(const float* __restrict__ rb, const float* __restrict__ qb,
          float* __restrict__ out, int nb) {
    __shared__ float s_red[4];
    int q = blockIdx.x;
    int t = threadIdx.x;

    {   // reset fine histogram + ticket for next replay
        int idx = q * 128 + t;
        if (idx < MFINE_MAX) g_fine[idx] = 0.0f;
        if (idx == 0)        g_ticket = 0u;
    }

    float Q    = __ldg(qb + q);
    float invq = 1.0f / (Q + 1e-10f);
    float acc  = 0.0f;
    for (int k = t; k < nb; k += 128)
        acc += g_A[k] * sinf(Q * __ldg(rb + k));

    #pragma unroll
    for (int o = 16; o > 0; o >>= 1)
        acc += __shfl_xor_sync(0xffffffff, acc, o);
    if ((t & 31) == 0) s_red[t >> 5] = acc;
    __syncthreads();
    if (t == 0) {
        float S = 1.0f + invq * (s_red[0] + s_red[1] + s_red[2] + s_red[3]);
        out[nb + q]     = S;
        out[2 * nb + q] = Q * (S - 1.0f);
    }
}

// ---------------------------------------------------------------------------
extern "C" void kernel_launch(void* const* d_in, const int* in_sizes, int n_in,
                              void* d_out, int out_size) {
    const float* pos  = (const float*)d_in[0];
    const float* cell = (const float*)d_in[1];
    const float* rb   = (const float*)d_in[2];
    const float* qb   = (const float*)d_in[3];
    float* out = (float*)d_out;

    int N  = in_sizes[0] / 3;
    int nb = in_sizes[2];
    float n_pairs = 0.5f * (float)N * (float)(N - 1);

    hist_kernel<<<HGRID, 256>>>(pos, cell, rb, N, nb);
    conv_kernel<<<nb, 128>>>(cell, rb, out, nb, N, n_pairs);
    sf_kernel<<<nb, 128>>>(rb, qb, out, nb);
}